// round 8
// baseline (speedup 1.0000x reference)
#include <cuda_runtime.h>
#include <cuda_fp16.h>
#include <math.h>
#include <stdint.h>

// ---------------- problem constants ----------------
#define BATCH 16
#define HH 56
#define WW 56
#define NTOK 3136            // 56*56
#define CDIM 384
#define HEADS 12
#define HD 32
#define WS 7
#define LWIN 49
#define HID 1536
#define MTOT 50176           // BATCH*NTOK = 392*128 = 196*256

// ---------------- scratch (static device memory; no allocations) ----------------
__device__ __align__(256) __half g_xw   [(size_t)MTOT * CDIM];       // LN1 + window partition
__device__ __align__(256) __half g_qkv  [(size_t)MTOT * 3 * CDIM];
__device__ __align__(256) __half g_attn [(size_t)MTOT * CDIM];       // attn out, window order
__device__ __align__(256) float  g_x2   [(size_t)MTOT * CDIM];       // fp32 residual spine
__device__ __align__(256) __half g_xn2  [(size_t)MTOT * CDIM];
__device__ __align__(256) __half g_h1   [(size_t)MTOT * HID];
__device__ __align__(256) __half g_h2   [(size_t)MTOT * HID];
// fp16 transposed weights: Wt[n][k] = W[k][n]
__device__ __align__(256) __half g_wqkv [(size_t)3 * CDIM * CDIM];
__device__ __align__(256) __half g_wproj[(size_t)CDIM * CDIM];
__device__ __align__(256) __half g_wfc1 [(size_t)HID * CDIM];
__device__ __align__(256) __half g_wfc2 [(size_t)CDIM * HID];

// ---------------- helpers ----------------
__device__ __forceinline__ uint32_t smem_u32(const void* p)
{
    uint32_t a;
    asm("{ .reg .u64 t; cvta.to.shared.u64 t, %1; cvt.u32.u64 %0, t; }" : "=r"(a) : "l"(p));
    return a;
}

#define CP_ASYNC16(dst, src) \
    asm volatile("cp.async.cg.shared.global [%0], [%1], 16;" :: "r"(dst), "l"(src))
#define CP_COMMIT() asm volatile("cp.async.commit_group;" ::: "memory")
#define CP_WAIT1()  asm volatile("cp.async.wait_group 1;" ::: "memory")

#define LDSM_X4(r0, r1, r2, r3, addr) \
    asm volatile("ldmatrix.sync.aligned.m8n8.x4.shared.b16 {%0,%1,%2,%3}, [%4];" \
                 : "=r"(r0), "=r"(r1), "=r"(r2), "=r"(r3) : "r"(addr))

#define MMA16816(c, a, b) \
    asm volatile("mma.sync.aligned.m16n8k16.row.col.f32.f16.f16.f32 " \
                 "{%0,%1,%2,%3}, {%4,%5,%6,%7}, {%8,%9}, {%0,%1,%2,%3};" \
                 : "+f"((c)[0]), "+f"((c)[1]), "+f"((c)[2]), "+f"((c)[3]) \
                 : "r"((a)[0]), "r"((a)[1]), "r"((a)[2]), "r"((a)[3]), \
                   "r"((b)[0]), "r"((b)[1]))

// window-order row -> spatial row (window reverse, NO un-shift, per reference)
__device__ __forceinline__ int map_win_to_spatial(int row)
{
    int b  = row / NTOK;
    int t  = row - b * NTOK;
    int wi = t / LWIN;
    int p  = t - wi * LWIN;
    int pr = p / WS;
    int pc = p - pr * WS;
    int h  = (wi >> 3) * WS + pr;
    int w  = (wi & 7)  * WS + pc;
    return b * NTOK + h * WW + w;
}

// ---------------- weight prep: fp32 [K,N] -> fp16 [N,K] (transpose) ----------------
__global__ __launch_bounds__(256)
void wprep(const float* __restrict__ W, __half* __restrict__ Wt, int K, int N)
{
    __shared__ float t[32][33];
    int k0 = blockIdx.y * 32, n0 = blockIdx.x * 32;
    int tx = threadIdx.x, ty = threadIdx.y;   // 32 x 8
#pragma unroll
    for (int i = 0; i < 32; i += 8)
        t[ty + i][tx] = W[(size_t)(k0 + ty + i) * N + n0 + tx];
    __syncthreads();
#pragma unroll
    for (int i = 0; i < 32; i += 8)
        Wt[(size_t)(n0 + ty + i) * K + k0 + tx] = __float2half(t[tx][ty + i]);
}

// ---------------- LayerNorm: warp per row (optionally fused shift + window partition) -------
template <bool SHIFT>
__global__ __launch_bounds__(256)
void ln_kernel(const float* __restrict__ x, const float* __restrict__ g,
               const float* __restrict__ b, __half* __restrict__ out)
{
    const int warp = threadIdx.x >> 5;
    const int lane = threadIdx.x & 31;
    const int row  = blockIdx.x * 8 + warp;
    int srow;
    if (SHIFT) {
        int bb = row / NTOK;
        int t  = row - bb * NTOK;
        int wi = t / LWIN;
        int p  = t - wi * LWIN;
        int pr = p / WS;
        int pc = p - pr * WS;
        int h  = (wi >> 3) * WS + pr + 3; if (h >= HH) h -= HH;
        int w  = (wi & 7)  * WS + pc + 3; if (w >= WW) w -= WW;
        srow = bb * NTOK + h * WW + w;
    } else {
        srow = row;
    }
    const float4* xr = (const float4*)(x + (size_t)srow * CDIM);
    float4 v[3];
    float s = 0.0f, ss = 0.0f;
#pragma unroll
    for (int w = 0; w < 3; w++) {
        v[w] = xr[lane + w * 32];
        s  += v[w].x + v[w].y + v[w].z + v[w].w;
        ss += v[w].x * v[w].x + v[w].y * v[w].y + v[w].z * v[w].z + v[w].w * v[w].w;
    }
#pragma unroll
    for (int off = 16; off; off >>= 1) {
        s  += __shfl_xor_sync(0xffffffffu, s,  off);
        ss += __shfl_xor_sync(0xffffffffu, ss, off);
    }
    const float m   = s * (1.0f / CDIM);
    const float inv = rsqrtf(ss * (1.0f / CDIM) - m * m + 1e-5f);
    uint2* o = (uint2*)(out + (size_t)row * CDIM);
    const float4* gp = (const float4*)g;
    const float4* bp = (const float4*)b;
#pragma unroll
    for (int w = 0; w < 3; w++) {
        float4 gg = gp[lane + w * 32];
        float4 bb = bp[lane + w * 32];
        float o0 = (v[w].x - m) * inv * gg.x + bb.x;
        float o1 = (v[w].y - m) * inv * gg.y + bb.y;
        float o2 = (v[w].z - m) * inv * gg.z + bb.z;
        float o3 = (v[w].w - m) * inv * gg.w + bb.w;
        uint2 u;
        ((__half2*)&u)[0] = __floats2half2_rn(o0, o1);
        ((__half2*)&u)[1] = __floats2half2_rn(o2, o3);
        o[lane + w * 32] = u;
    }
}

// ---------------- fp16 HMMA GEMM: C(MxN) = A(MxK) * Bw(NxK)^T, fp32 accumulate -------------
// CTA tile 256x128x64, warp tile 64x64 (8 warps), 3-stage cp.async, 1 CTA/SM, 144KB smem.
// MODE 0: C fp16, no bias    MODE 1: C fp16 + bias
// MODE 2: C fp32 + bias + win->spatial scatter + residual
// MODE 3: C fp32 + bias + residual (same row)
#define BMM 256
#define BNN 128
#define BKK 64
#define STG 3
#define A_STG 32768                        // 256 rows * 128 B
#define B_STG 16384                        // 128 rows * 128 B
#define GEMM_SMEM (STG * (A_STG + B_STG))  // 147456

template <int MODE, int K, int N>
__global__ __launch_bounds__(256, 1)
void hgemm(const __half* __restrict__ A, const __half* __restrict__ Bw,
           void* __restrict__ Cout, const float* __restrict__ bias,
           const float* __restrict__ resid)
{
    extern __shared__ char smem[];
    const uint32_t sA = smem_u32(smem);
    const uint32_t sB = sA + STG * A_STG;

    const int tid  = threadIdx.x;
    const int wid  = tid >> 5;
    const int lane = tid & 31;
    const int bm   = blockIdx.y * BMM;
    const int bn   = blockIdx.x * BNN;
    const int wm0  = (wid & 3) * 64;   // warp row offset in tile (4 row groups)
    const int wn0  = (wid >> 2) * 64;  // warp col offset in tile (2 col groups)

    // global->smem: 16B chunks; chunk (r0 + q*32, lc), swizzle constant across q
    const int lc = tid & 7;
    const int r0 = tid >> 3;           // 0..31
    const uint32_t soff = (uint32_t)r0 * 128 + (uint32_t)((lc ^ (r0 & 7)) << 4);

    constexpr int NC = K / BKK;

    // prologue: stages 0,1
#pragma unroll
    for (int c = 0; c < 2; c++) {
        const __half* Ag = A  + (size_t)(bm + r0) * K + c * BKK + lc * 8;
        const __half* Bg = Bw + (size_t)(bn + r0) * K + c * BKK + lc * 8;
        uint32_t da = sA + c * A_STG + soff;
        uint32_t db = sB + c * B_STG + soff;
#pragma unroll
        for (int q = 0; q < 8; q++)
            CP_ASYNC16(da + q * 4096, Ag + (size_t)(q * 32) * K);
#pragma unroll
        for (int q = 0; q < 4; q++)
            CP_ASYNC16(db + q * 4096, Bg + (size_t)(q * 32) * K);
        CP_COMMIT();
    }

    float acc[4][8][4];
#pragma unroll
    for (int i = 0; i < 4; i++)
#pragma unroll
        for (int j = 0; j < 8; j++)
#pragma unroll
            for (int r = 0; r < 4; r++) acc[i][j][r] = 0.0f;

    // per-lane ldmatrix row/chunk components
    const int a_row_l = lane & 15;                              // + fi*16
    const int a_chk_l = (lane >> 4) & 1;                        // + 2*ks
    const int b_row_l = (((lane >> 4) & 1) << 3) + (lane & 7);  // + nj*16
    const int b_chk_l = (lane >> 3) & 1;                        // + 2*ks

#pragma unroll 1
    for (int c = 0; c < NC; c++) {
        const int st = c % STG;
        CP_WAIT1();
        __syncthreads();   // orders stage-c reads before anyone refills it

        if (c + 2 < NC) {
            const int cc = c + 2, s2 = cc % STG;
            const __half* Ag = A  + (size_t)(bm + r0) * K + cc * BKK + lc * 8;
            const __half* Bg = Bw + (size_t)(bn + r0) * K + cc * BKK + lc * 8;
            uint32_t da = sA + s2 * A_STG + soff;
            uint32_t db = sB + s2 * B_STG + soff;
#pragma unroll
            for (int q = 0; q < 8; q++)
                CP_ASYNC16(da + q * 4096, Ag + (size_t)(q * 32) * K);
#pragma unroll
            for (int q = 0; q < 4; q++)
                CP_ASYNC16(db + q * 4096, Bg + (size_t)(q * 32) * K);
        }
        CP_COMMIT();

        const uint32_t ab = sA + st * A_STG;
        const uint32_t bb = sB + st * B_STG;
#pragma unroll
        for (int ks = 0; ks < 4; ks++) {
            uint32_t a[4][4], b[8][2];
#pragma unroll
            for (int fi = 0; fi < 4; fi++) {
                int row = wm0 + fi * 16 + a_row_l;
                int chk = 2 * ks + a_chk_l;
                uint32_t ad = ab + (uint32_t)row * 128 + (uint32_t)((chk ^ (row & 7)) << 4);
                LDSM_X4(a[fi][0], a[fi][1], a[fi][2], a[fi][3], ad);
            }
#pragma unroll
            for (int nj = 0; nj < 4; nj++) {
                int row = wn0 + nj * 16 + b_row_l;
                int chk = 2 * ks + b_chk_l;
                uint32_t bd = bb + (uint32_t)row * 128 + (uint32_t)((chk ^ (row & 7)) << 4);
                LDSM_X4(b[nj * 2][0], b[nj * 2][1], b[nj * 2 + 1][0], b[nj * 2 + 1][1], bd);
            }
#pragma unroll
            for (int fi = 0; fi < 4; fi++)
#pragma unroll
                for (int j = 0; j < 8; j++)
                    MMA16816(acc[fi][j], a[fi], b[j]);
        }
    }

    // ---------------- epilogue ----------------
#pragma unroll
    for (int fi = 0; fi < 4; fi++) {
#pragma unroll
        for (int h = 0; h < 2; h++) {
            int row  = bm + wm0 + fi * 16 + (lane >> 2) + h * 8;
            int orow = (MODE == 2) ? map_win_to_spatial(row) : row;
#pragma unroll
            for (int j = 0; j < 8; j++) {
                int col = bn + wn0 + j * 8 + (lane & 3) * 2;
                float v0 = acc[fi][j][h * 2];
                float v1 = acc[fi][j][h * 2 + 1];
                if (MODE >= 1) { v0 += bias[col]; v1 += bias[col + 1]; }
                if (MODE >= 2) {
                    const float* rp = resid + (size_t)orow * N + col;
                    float2 rr = *(const float2*)rp;
                    float2 o; o.x = v0 + rr.x; o.y = v1 + rr.y;
                    *(float2*)((float*)Cout + (size_t)orow * N + col) = o;
                } else {
                    *(__half2*)((__half*)Cout + (size_t)row * N + col) =
                        __floats2half2_rn(v0, v1);
                }
            }
        }
    }
}

// ---------------- windowed attention: one block per (window, head), half2-resident --------
__global__ __launch_bounds__(256)
void attn_kernel(const __half* __restrict__ qkv, __half* __restrict__ out)
{
    const int win  = blockIdx.x;
    const int head = blockIdx.y;
    const int tid  = threadIdx.x;

    __shared__ __half2 qh[LWIN * 17];
    __shared__ __half2 kh[LWIN * 17];
    __shared__ __half2 vh[LWIN * 17];
    __shared__ float   sc[LWIN * 52];
    __shared__ int     rg[LWIN];

    const float scale = 0.17677669529663687f;  // 1/sqrt(32)
    const size_t base = (size_t)win * LWIN * (3 * CDIM) + head * HD;

    for (int idx = tid; idx < LWIN * 16; idx += 256) {
        int p = idx >> 4, d2 = idx & 15;
        const __half2* r = (const __half2*)(qkv + base + (size_t)p * (3 * CDIM));
        qh[p * 17 + d2] = r[d2];
        kh[p * 17 + d2] = r[CDIM / 2 + d2];
        vh[p * 17 + d2] = r[CDIM + d2];
    }
    if (tid < LWIN) {
        int wi = win & 63;
        int h = (wi >> 3) * WS + tid / WS;
        int w = (wi & 7)  * WS + tid % WS;
        int sh = (h < HH - WS) ? 0 : ((h < HH - 3) ? 1 : 2);
        int sw = (w < WW - WS) ? 0 : ((w < WW - 3) ? 1 : 2);
        rg[tid] = sh * 3 + sw;
    }
    __syncthreads();

    // scores = (q @ k^T) * scale + mask
    for (int idx = tid; idx < LWIN * LWIN; idx += 256) {
        int i = idx / LWIN, j = idx - i * LWIN;
        float s = 0.0f;
#pragma unroll
        for (int d2 = 0; d2 < 16; d2++) {
            float2 a = __half22float2(qh[i * 17 + d2]);
            float2 b = __half22float2(kh[j * 17 + d2]);
            s = fmaf(a.x, b.x, s);
            s = fmaf(a.y, b.y, s);
        }
        s *= scale;
        if (rg[i] != rg[j]) s -= 100.0f;
        sc[i * 52 + j] = s;
    }
    __syncthreads();

    // softmax rows (one warp per row)
    int wid = tid >> 5, lane = tid & 31;
    for (int i = wid; i < LWIN; i += 8) {
        float v0 = (lane < LWIN)      ? sc[i * 52 + lane]      : -1e30f;
        float v1 = (lane + 32 < LWIN) ? sc[i * 52 + lane + 32] : -1e30f;
        float m = fmaxf(v0, v1);
#pragma unroll
        for (int off = 16; off; off >>= 1) m = fmaxf(m, __shfl_xor_sync(0xffffffffu, m, off));
        float e0 = (lane < LWIN)      ? __expf(v0 - m) : 0.0f;
        float e1 = (lane + 32 < LWIN) ? __expf(v1 - m) : 0.0f;
        float s = e0 + e1;
#pragma unroll
        for (int off = 16; off; off >>= 1) s += __shfl_xor_sync(0xffffffffu, s, off);
        float r = 1.0f / s;
        if (lane < LWIN)      sc[i * 52 + lane]      = e0 * r;
        if (lane + 32 < LWIN) sc[i * 52 + lane + 32] = e1 * r;
    }
    __syncthreads();

    // out = softmax @ v
    for (int idx = tid; idx < LWIN * 16; idx += 256) {
        int i = idx >> 4, d2 = idx & 15;
        float ox = 0.0f, oy = 0.0f;
#pragma unroll 7
        for (int j = 0; j < LWIN; j++) {
            float p = sc[i * 52 + j];
            float2 v = __half22float2(vh[j * 17 + d2]);
            ox = fmaf(p, v.x, ox);
            oy = fmaf(p, v.y, oy);
        }
        *(__half2*)(out + (size_t)(win * LWIN + i) * CDIM + head * HD + 2 * d2) =
            __floats2half2_rn(ox, oy);
    }
}

// ---------------- depthwise 3x3 conv (NHWC, half2: 2 channels/thread) + bias + GELU --------
__global__ __launch_bounds__(256)
void dwconv_gelu(const __half* __restrict__ x, const float* __restrict__ kern,
                 const float* __restrict__ bias, __half* __restrict__ out)
{
    int c2 = blockIdx.x * 256 + threadIdx.x;   // 0..767 (pair index)
    int ch = c2 * 2;
    int hw = blockIdx.y;
    int b  = blockIdx.z;
    int h = hw / WW, w = hw - h * WW;

    const float* kp0 = kern + ch * 9;
    const float* kp1 = kern + ch * 9 + 9;
    float2 bb = *(const float2*)(bias + ch);
    float a0 = bb.x, a1 = bb.y;
    size_t brow = (size_t)b * NTOK;
#pragma unroll
    for (int dh = -1; dh <= 1; dh++) {
        int ih = h + dh;
        if ((unsigned)ih >= HH) continue;
#pragma unroll
        for (int dw = -1; dw <= 1; dw++) {
            int iw = w + dw;
            if ((unsigned)iw >= WW) continue;
            float2 v = __half22float2(*(const __half2*)(x + (brow + ih * WW + iw) * HID + ch));
            int ki = (dh + 1) * 3 + (dw + 1);
            a0 = fmaf(v.x, kp0[ki], a0);
            a1 = fmaf(v.y, kp1[ki], a1);
        }
    }
    float g0 = 0.5f * a0 * (1.0f + erff(a0 * 0.70710678118654752f));
    float g1 = 0.5f * a1 * (1.0f + erff(a1 * 0.70710678118654752f));
    *(__half2*)(out + (brow + hw) * HID + ch) = __floats2half2_rn(g0, g1);
}

// ---------------- launcher ----------------
extern "C" void kernel_launch(void* const* d_in, const int* in_sizes, int n_in,
                              void* d_out, int out_size)
{
    const float* x     = (const float*)d_in[0];
    const float* ln1g  = (const float*)d_in[1];
    const float* ln1b  = (const float*)d_in[2];
    const float* qkvw  = (const float*)d_in[3];
    const float* projw = (const float*)d_in[4];
    const float* projb = (const float*)d_in[5];
    const float* ln2g  = (const float*)d_in[6];
    const float* ln2b  = (const float*)d_in[7];
    const float* fc1w  = (const float*)d_in[8];
    const float* fc1b  = (const float*)d_in[9];
    const float* dwk   = (const float*)d_in[10];
    const float* dwb   = (const float*)d_in[11];
    const float* fc2w  = (const float*)d_in[12];
    const float* fc2b  = (const float*)d_in[13];
    float* out = (float*)d_out;

    __half *xw, *qkv, *attn, *xn2, *h1, *h2, *wqkv, *wproj, *wfc1, *wfc2;
    float  *x2;
    cudaGetSymbolAddress((void**)&xw,    g_xw);
    cudaGetSymbolAddress((void**)&qkv,   g_qkv);
    cudaGetSymbolAddress((void**)&attn,  g_attn);
    cudaGetSymbolAddress((void**)&x2,    g_x2);
    cudaGetSymbolAddress((void**)&xn2,   g_xn2);
    cudaGetSymbolAddress((void**)&h1,    g_h1);
    cudaGetSymbolAddress((void**)&h2,    g_h2);
    cudaGetSymbolAddress((void**)&wqkv,  g_wqkv);
    cudaGetSymbolAddress((void**)&wproj, g_wproj);
    cudaGetSymbolAddress((void**)&wfc1,  g_wfc1);
    cudaGetSymbolAddress((void**)&wfc2,  g_wfc2);

    cudaFuncSetAttribute(hgemm<0, CDIM, 3 * CDIM>, cudaFuncAttributeMaxDynamicSharedMemorySize, GEMM_SMEM);
    cudaFuncSetAttribute(hgemm<2, CDIM, CDIM>,     cudaFuncAttributeMaxDynamicSharedMemorySize, GEMM_SMEM);
    cudaFuncSetAttribute(hgemm<1, CDIM, HID>,      cudaFuncAttributeMaxDynamicSharedMemorySize, GEMM_SMEM);
    cudaFuncSetAttribute(hgemm<3, HID, CDIM>,      cudaFuncAttributeMaxDynamicSharedMemorySize, GEMM_SMEM);

    // Launch order interleaves weight-prep with compute so ncu (-s 5 -c 1)
    // captures launch #5 = proj hgemm (all dependencies still satisfied).
    // 0: wprep qkv
    wprep<<<dim3(1152 / 32, 384 / 32),  dim3(32, 8)>>>(qkvw,  wqkv,  384, 1152);
    // 1: LN1 + roll(-3,-3) + window partition (fp16 out)
    ln_kernel<true><<<MTOT / 8, 256>>>(x, ln1g, ln1b, xw);
    // 2: QKV GEMM
    hgemm<0, CDIM, 3 * CDIM><<<dim3(9, MTOT / 256), 256, GEMM_SMEM>>>(xw, wqkv, qkv, (const float*)0, (const float*)0);
    // 3: wprep proj
    wprep<<<dim3(384 / 32,  384 / 32),  dim3(32, 8)>>>(projw, wproj, 384, 384);
    // 4: windowed attention with analytic shift mask
    attn_kernel<<<dim3(1024, HEADS), 256>>>(qkv, attn);
    // 5: proj GEMM + bias + window-reverse scatter + residual(x) -> x2 (fp32)   [ncu target]
    hgemm<2, CDIM, CDIM><<<dim3(3, MTOT / 256), 256, GEMM_SMEM>>>(attn, wproj, x2, projb, x);
    // 6: wprep fc1
    wprep<<<dim3(1536 / 32, 384 / 32),  dim3(32, 8)>>>(fc1w,  wfc1,  384, 1536);
    // 7: LN2 (fp16 out)
    ln_kernel<false><<<MTOT / 8, 256>>>(x2, ln2g, ln2b, xn2);
    // 8: fc1 GEMM + bias
    hgemm<1, CDIM, HID><<<dim3(12, MTOT / 256), 256, GEMM_SMEM>>>(xn2, wfc1, h1, fc1b, (const float*)0);
    // 9: wprep fc2
    wprep<<<dim3(384 / 32,  1536 / 32), dim3(32, 8)>>>(fc2w,  wfc2,  1536, 384);
    // 10: depthwise conv + bias + exact GELU (half2)
    dwconv_gelu<<<dim3(3, NTOK, BATCH), 256>>>(h1, dwk, dwb, h2);
    // 11: fc2 GEMM + bias + residual(x2) -> out (fp32)
    hgemm<3, HID, CDIM><<<dim3(3, MTOT / 256), 256, GEMM_SMEM>>>(h2, wfc2, out, fc2b, x2);
}

// round 9
// speedup vs baseline: 1.0271x; 1.0271x over previous
#include <cuda_runtime.h>
#include <cuda_fp16.h>
#include <math.h>
#include <stdint.h>

// ---------------- problem constants ----------------
#define BATCH 16
#define HH 56
#define WW 56
#define NTOK 3136            // 56*56
#define CDIM 384
#define HEADS 12
#define HD 32
#define WS 7
#define LWIN 49
#define HID 1536
#define MTOT 50176           // BATCH*NTOK = 392*128 = 196*256

// ---------------- scratch (static device memory; no allocations) ----------------
__device__ __align__(256) __half g_xw   [(size_t)MTOT * CDIM];       // LN1 + window partition
__device__ __align__(256) __half g_qkv  [(size_t)MTOT * 3 * CDIM];
__device__ __align__(256) __half g_attn [(size_t)MTOT * CDIM];       // attn out, window order
__device__ __align__(256) float  g_x2   [(size_t)MTOT * CDIM];       // fp32 residual spine
__device__ __align__(256) __half g_xn2  [(size_t)MTOT * CDIM];
__device__ __align__(256) __half g_h1   [(size_t)MTOT * HID];
__device__ __align__(256) __half g_h2   [(size_t)MTOT * HID];
// fp16 transposed weights: Wt[n][k] = W[k][n]
__device__ __align__(256) __half g_wqkv [(size_t)3 * CDIM * CDIM];
__device__ __align__(256) __half g_wproj[(size_t)CDIM * CDIM];
__device__ __align__(256) __half g_wfc1 [(size_t)HID * CDIM];
__device__ __align__(256) __half g_wfc2 [(size_t)CDIM * HID];

// ---------------- helpers ----------------
__device__ __forceinline__ uint32_t smem_u32(const void* p)
{
    uint32_t a;
    asm("{ .reg .u64 t; cvta.to.shared.u64 t, %1; cvt.u32.u64 %0, t; }" : "=r"(a) : "l"(p));
    return a;
}

#define CP_ASYNC16(dst, src) \
    asm volatile("cp.async.cg.shared.global [%0], [%1], 16;" :: "r"(dst), "l"(src))
#define CP_COMMIT() asm volatile("cp.async.commit_group;" ::: "memory")
#define CP_WAIT1()  asm volatile("cp.async.wait_group 1;" ::: "memory")

#define LDSM_X4(r0, r1, r2, r3, addr) \
    asm volatile("ldmatrix.sync.aligned.m8n8.x4.shared.b16 {%0,%1,%2,%3}, [%4];" \
                 : "=r"(r0), "=r"(r1), "=r"(r2), "=r"(r3) : "r"(addr))

#define MMA16816(c, a, b) \
    asm volatile("mma.sync.aligned.m16n8k16.row.col.f32.f16.f16.f32 " \
                 "{%0,%1,%2,%3}, {%4,%5,%6,%7}, {%8,%9}, {%0,%1,%2,%3};" \
                 : "+f"((c)[0]), "+f"((c)[1]), "+f"((c)[2]), "+f"((c)[3]) \
                 : "r"((a)[0]), "r"((a)[1]), "r"((a)[2]), "r"((a)[3]), \
                   "r"((b)[0]), "r"((b)[1]))

// window-order row -> spatial row (window reverse, NO un-shift, per reference)
__device__ __forceinline__ int map_win_to_spatial(int row)
{
    int b  = row / NTOK;
    int t  = row - b * NTOK;
    int wi = t / LWIN;
    int p  = t - wi * LWIN;
    int pr = p / WS;
    int pc = p - pr * WS;
    int h  = (wi >> 3) * WS + pr;
    int w  = (wi & 7)  * WS + pc;
    return b * NTOK + h * WW + w;
}

// ---------------- weight prep: fp32 [K,N] -> fp16 [N,K] (transpose) ----------------
__global__ __launch_bounds__(256)
void wprep(const float* __restrict__ W, __half* __restrict__ Wt, int K, int N)
{
    __shared__ float t[32][33];
    int k0 = blockIdx.y * 32, n0 = blockIdx.x * 32;
    int tx = threadIdx.x, ty = threadIdx.y;   // 32 x 8
#pragma unroll
    for (int i = 0; i < 32; i += 8)
        t[ty + i][tx] = W[(size_t)(k0 + ty + i) * N + n0 + tx];
    __syncthreads();
#pragma unroll
    for (int i = 0; i < 32; i += 8)
        Wt[(size_t)(n0 + ty + i) * K + k0 + tx] = __float2half(t[tx][ty + i]);
}

// ---------------- LayerNorm: warp per row (optionally fused shift + window partition) -------
template <bool SHIFT>
__global__ __launch_bounds__(256)
void ln_kernel(const float* __restrict__ x, const float* __restrict__ g,
               const float* __restrict__ b, __half* __restrict__ out)
{
    const int warp = threadIdx.x >> 5;
    const int lane = threadIdx.x & 31;
    const int row  = blockIdx.x * 8 + warp;
    int srow;
    if (SHIFT) {
        int bb = row / NTOK;
        int t  = row - bb * NTOK;
        int wi = t / LWIN;
        int p  = t - wi * LWIN;
        int pr = p / WS;
        int pc = p - pr * WS;
        int h  = (wi >> 3) * WS + pr + 3; if (h >= HH) h -= HH;
        int w  = (wi & 7)  * WS + pc + 3; if (w >= WW) w -= WW;
        srow = bb * NTOK + h * WW + w;
    } else {
        srow = row;
    }
    const float4* xr = (const float4*)(x + (size_t)srow * CDIM);
    float4 v[3];
    float s = 0.0f, ss = 0.0f;
#pragma unroll
    for (int w = 0; w < 3; w++) {
        v[w] = xr[lane + w * 32];
        s  += v[w].x + v[w].y + v[w].z + v[w].w;
        ss += v[w].x * v[w].x + v[w].y * v[w].y + v[w].z * v[w].z + v[w].w * v[w].w;
    }
#pragma unroll
    for (int off = 16; off; off >>= 1) {
        s  += __shfl_xor_sync(0xffffffffu, s,  off);
        ss += __shfl_xor_sync(0xffffffffu, ss, off);
    }
    const float m   = s * (1.0f / CDIM);
    const float inv = rsqrtf(ss * (1.0f / CDIM) - m * m + 1e-5f);
    uint2* o = (uint2*)(out + (size_t)row * CDIM);
    const float4* gp = (const float4*)g;
    const float4* bp = (const float4*)b;
#pragma unroll
    for (int w = 0; w < 3; w++) {
        float4 gg = gp[lane + w * 32];
        float4 bb = bp[lane + w * 32];
        float o0 = (v[w].x - m) * inv * gg.x + bb.x;
        float o1 = (v[w].y - m) * inv * gg.y + bb.y;
        float o2 = (v[w].z - m) * inv * gg.z + bb.z;
        float o3 = (v[w].w - m) * inv * gg.w + bb.w;
        uint2 u;
        ((__half2*)&u)[0] = __floats2half2_rn(o0, o1);
        ((__half2*)&u)[1] = __floats2half2_rn(o2, o3);
        o[lane + w * 32] = u;
    }
}

// ---------------- fp16 HMMA GEMM: C(MxN) = A(MxK) * Bw(NxK)^T, fp32 accumulate -------------
// CTA tile 256x128x64, warp tile 64x64 (8 warps), 3-stage cp.async, 1 CTA/SM, 144KB smem.
// Mainloop unrolled by 3 (= STG) so stage indices are compile-time constants.
// MODE 0: C fp16, no bias    MODE 1: C fp16 + bias
// MODE 2: C fp32 + bias + win->spatial scatter + residual
// MODE 3: C fp32 + bias + residual (same row)
#define BMM 256
#define BNN 128
#define BKK 64
#define STG 3
#define A_STG 32768                        // 256 rows * 128 B
#define B_STG 16384                        // 128 rows * 128 B
#define GEMM_SMEM (STG * (A_STG + B_STG))  // 147456

template <int MODE, int K, int N>
__global__ __launch_bounds__(256, 1)
void hgemm(const __half* __restrict__ A, const __half* __restrict__ Bw,
           void* __restrict__ Cout, const float* __restrict__ bias,
           const float* __restrict__ resid)
{
    extern __shared__ char smem[];
    const uint32_t sA = smem_u32(smem);
    const uint32_t sB = sA + STG * A_STG;

    const int tid  = threadIdx.x;
    const int wid  = tid >> 5;
    const int lane = tid & 31;
    const int bm   = blockIdx.y * BMM;
    const int bn   = blockIdx.x * BNN;
    const int wm0  = (wid & 3) * 64;   // warp row offset in tile (4 row groups)
    const int wn0  = (wid >> 2) * 64;  // warp col offset in tile (2 col groups)

    // global->smem: 16B chunks; chunk (r0 + q*32, lc), swizzle constant across q
    const int lc = tid & 7;
    const int r0 = tid >> 3;           // 0..31
    const uint32_t soff = (uint32_t)r0 * 128 + (uint32_t)((lc ^ (r0 & 7)) << 4);

    constexpr int NC = K / BKK;        // 6 or 24 — divisible by 3

    // prologue: stages 0,1
#pragma unroll
    for (int c = 0; c < 2; c++) {
        const __half* Ag = A  + (size_t)(bm + r0) * K + c * BKK + lc * 8;
        const __half* Bg = Bw + (size_t)(bn + r0) * K + c * BKK + lc * 8;
        uint32_t da = sA + c * A_STG + soff;
        uint32_t db = sB + c * B_STG + soff;
#pragma unroll
        for (int q = 0; q < 8; q++)
            CP_ASYNC16(da + q * 4096, Ag + (size_t)(q * 32) * K);
#pragma unroll
        for (int q = 0; q < 4; q++)
            CP_ASYNC16(db + q * 4096, Bg + (size_t)(q * 32) * K);
        CP_COMMIT();
    }

    float acc[4][8][4];
#pragma unroll
    for (int i = 0; i < 4; i++)
#pragma unroll
        for (int j = 0; j < 8; j++)
#pragma unroll
            for (int r = 0; r < 4; r++) acc[i][j][r] = 0.0f;

    // per-lane ldmatrix row/chunk components
    const int a_row_l = lane & 15;                              // + fi*16
    const int a_chk_l = (lane >> 4) & 1;                        // + 2*ks
    const int b_row_l = (((lane >> 4) & 1) << 3) + (lane & 7);  // + nj*16
    const int b_chk_l = (lane >> 3) & 1;                        // + 2*ks

#pragma unroll 3
    for (int c = 0; c < NC; c++) {
        const int st = c % STG;        // compile-time constant within each unrolled copy
        CP_WAIT1();
        __syncthreads();               // orders stage-c reads before anyone refills it

        if (c + 2 < NC) {
            const int cc = c + 2, s2 = cc % STG;
            const __half* Ag = A  + (size_t)(bm + r0) * K + cc * BKK + lc * 8;
            const __half* Bg = Bw + (size_t)(bn + r0) * K + cc * BKK + lc * 8;
            uint32_t da = sA + s2 * A_STG + soff;
            uint32_t db = sB + s2 * B_STG + soff;
#pragma unroll
            for (int q = 0; q < 8; q++)
                CP_ASYNC16(da + q * 4096, Ag + (size_t)(q * 32) * K);
#pragma unroll
            for (int q = 0; q < 4; q++)
                CP_ASYNC16(db + q * 4096, Bg + (size_t)(q * 32) * K);
        }
        CP_COMMIT();

        const uint32_t ab = sA + st * A_STG;
        const uint32_t bb = sB + st * B_STG;
#pragma unroll
        for (int ks = 0; ks < 4; ks++) {
            uint32_t a[4][4], b[8][2];
#pragma unroll
            for (int fi = 0; fi < 4; fi++) {
                int row = wm0 + fi * 16 + a_row_l;
                int chk = 2 * ks + a_chk_l;
                uint32_t ad = ab + (uint32_t)row * 128 + (uint32_t)((chk ^ (row & 7)) << 4);
                LDSM_X4(a[fi][0], a[fi][1], a[fi][2], a[fi][3], ad);
            }
#pragma unroll
            for (int nj = 0; nj < 4; nj++) {
                int row = wn0 + nj * 16 + b_row_l;
                int chk = 2 * ks + b_chk_l;
                uint32_t bd = bb + (uint32_t)row * 128 + (uint32_t)((chk ^ (row & 7)) << 4);
                LDSM_X4(b[nj * 2][0], b[nj * 2][1], b[nj * 2 + 1][0], b[nj * 2 + 1][1], bd);
            }
#pragma unroll
            for (int fi = 0; fi < 4; fi++)
#pragma unroll
                for (int j = 0; j < 8; j++)
                    MMA16816(acc[fi][j], a[fi], b[j]);
        }
    }

    // ---------------- epilogue ----------------
#pragma unroll
    for (int fi = 0; fi < 4; fi++) {
#pragma unroll
        for (int h = 0; h < 2; h++) {
            int row  = bm + wm0 + fi * 16 + (lane >> 2) + h * 8;
            int orow = (MODE == 2) ? map_win_to_spatial(row) : row;
#pragma unroll
            for (int j = 0; j < 8; j++) {
                int col = bn + wn0 + j * 8 + (lane & 3) * 2;
                float v0 = acc[fi][j][h * 2];
                float v1 = acc[fi][j][h * 2 + 1];
                if (MODE >= 1) { v0 += bias[col]; v1 += bias[col + 1]; }
                if (MODE >= 2) {
                    const float* rp = resid + (size_t)orow * N + col;
                    float2 rr = *(const float2*)rp;
                    float2 o; o.x = v0 + rr.x; o.y = v1 + rr.y;
                    *(float2*)((float*)Cout + (size_t)orow * N + col) = o;
                } else {
                    *(__half2*)((__half*)Cout + (size_t)row * N + col) =
                        __floats2half2_rn(v0, v1);
                }
            }
        }
    }
}

// ---------------- windowed attention: one block per (window, head), half2-resident --------
__global__ __launch_bounds__(256)
void attn_kernel(const __half* __restrict__ qkv, __half* __restrict__ out)
{
    const int win  = blockIdx.x;
    const int head = blockIdx.y;
    const int tid  = threadIdx.x;

    __shared__ __half2 qh[LWIN * 17];
    __shared__ __half2 kh[LWIN * 17];
    __shared__ __half2 vh[LWIN * 17];
    __shared__ float   sc[LWIN * 52];
    __shared__ int     rg[LWIN];

    const float scale = 0.17677669529663687f;  // 1/sqrt(32)
    const size_t base = (size_t)win * LWIN * (3 * CDIM) + head * HD;

    for (int idx = tid; idx < LWIN * 16; idx += 256) {
        int p = idx >> 4, d2 = idx & 15;
        const __half2* r = (const __half2*)(qkv + base + (size_t)p * (3 * CDIM));
        qh[p * 17 + d2] = r[d2];
        kh[p * 17 + d2] = r[CDIM / 2 + d2];
        vh[p * 17 + d2] = r[CDIM + d2];
    }
    if (tid < LWIN) {
        int wi = win & 63;
        int h = (wi >> 3) * WS + tid / WS;
        int w = (wi & 7)  * WS + tid % WS;
        int sh = (h < HH - WS) ? 0 : ((h < HH - 3) ? 1 : 2);
        int sw = (w < WW - WS) ? 0 : ((w < WW - 3) ? 1 : 2);
        rg[tid] = sh * 3 + sw;
    }
    __syncthreads();

    // scores = (q @ k^T) * scale + mask
    for (int idx = tid; idx < LWIN * LWIN; idx += 256) {
        int i = idx / LWIN, j = idx - i * LWIN;
        float s = 0.0f;
#pragma unroll
        for (int d2 = 0; d2 < 16; d2++) {
            float2 a = __half22float2(qh[i * 17 + d2]);
            float2 b = __half22float2(kh[j * 17 + d2]);
            s = fmaf(a.x, b.x, s);
            s = fmaf(a.y, b.y, s);
        }
        s *= scale;
        if (rg[i] != rg[j]) s -= 100.0f;
        sc[i * 52 + j] = s;
    }
    __syncthreads();

    // softmax rows (one warp per row)
    int wid = tid >> 5, lane = tid & 31;
    for (int i = wid; i < LWIN; i += 8) {
        float v0 = (lane < LWIN)      ? sc[i * 52 + lane]      : -1e30f;
        float v1 = (lane + 32 < LWIN) ? sc[i * 52 + lane + 32] : -1e30f;
        float m = fmaxf(v0, v1);
#pragma unroll
        for (int off = 16; off; off >>= 1) m = fmaxf(m, __shfl_xor_sync(0xffffffffu, m, off));
        float e0 = (lane < LWIN)      ? __expf(v0 - m) : 0.0f;
        float e1 = (lane + 32 < LWIN) ? __expf(v1 - m) : 0.0f;
        float s = e0 + e1;
#pragma unroll
        for (int off = 16; off; off >>= 1) s += __shfl_xor_sync(0xffffffffu, s, off);
        float r = 1.0f / s;
        if (lane < LWIN)      sc[i * 52 + lane]      = e0 * r;
        if (lane + 32 < LWIN) sc[i * 52 + lane + 32] = e1 * r;
    }
    __syncthreads();

    // out = softmax @ v
    for (int idx = tid; idx < LWIN * 16; idx += 256) {
        int i = idx >> 4, d2 = idx & 15;
        float ox = 0.0f, oy = 0.0f;
#pragma unroll 7
        for (int j = 0; j < LWIN; j++) {
            float p = sc[i * 52 + j];
            float2 v = __half22float2(vh[j * 17 + d2]);
            ox = fmaf(p, v.x, ox);
            oy = fmaf(p, v.y, oy);
        }
        *(__half2*)(out + (size_t)(win * LWIN + i) * CDIM + head * HD + 2 * d2) =
            __floats2half2_rn(ox, oy);
    }
}

// ---------------- depthwise 3x3 conv (NHWC, half2: 2 channels/thread) + bias + GELU --------
__global__ __launch_bounds__(256)
void dwconv_gelu(const __half* __restrict__ x, const float* __restrict__ kern,
                 const float* __restrict__ bias, __half* __restrict__ out)
{
    int c2 = blockIdx.x * 256 + threadIdx.x;   // 0..767 (pair index)
    int ch = c2 * 2;
    int hw = blockIdx.y;
    int b  = blockIdx.z;
    int h = hw / WW, w = hw - h * WW;

    const float* kp0 = kern + ch * 9;
    const float* kp1 = kern + ch * 9 + 9;
    float2 bb = *(const float2*)(bias + ch);
    float a0 = bb.x, a1 = bb.y;
    size_t brow = (size_t)b * NTOK;
#pragma unroll
    for (int dh = -1; dh <= 1; dh++) {
        int ih = h + dh;
        if ((unsigned)ih >= HH) continue;
#pragma unroll
        for (int dw = -1; dw <= 1; dw++) {
            int iw = w + dw;
            if ((unsigned)iw >= WW) continue;
            float2 v = __half22float2(*(const __half2*)(x + (brow + ih * WW + iw) * HID + ch));
            int ki = (dh + 1) * 3 + (dw + 1);
            a0 = fmaf(v.x, kp0[ki], a0);
            a1 = fmaf(v.y, kp1[ki], a1);
        }
    }
    float g0 = 0.5f * a0 * (1.0f + erff(a0 * 0.70710678118654752f));
    float g1 = 0.5f * a1 * (1.0f + erff(a1 * 0.70710678118654752f));
    *(__half2*)(out + (brow + hw) * HID + ch) = __floats2half2_rn(g0, g1);
}

// ---------------- launcher ----------------
extern "C" void kernel_launch(void* const* d_in, const int* in_sizes, int n_in,
                              void* d_out, int out_size)
{
    const float* x     = (const float*)d_in[0];
    const float* ln1g  = (const float*)d_in[1];
    const float* ln1b  = (const float*)d_in[2];
    const float* qkvw  = (const float*)d_in[3];
    const float* projw = (const float*)d_in[4];
    const float* projb = (const float*)d_in[5];
    const float* ln2g  = (const float*)d_in[6];
    const float* ln2b  = (const float*)d_in[7];
    const float* fc1w  = (const float*)d_in[8];
    const float* fc1b  = (const float*)d_in[9];
    const float* dwk   = (const float*)d_in[10];
    const float* dwb   = (const float*)d_in[11];
    const float* fc2w  = (const float*)d_in[12];
    const float* fc2b  = (const float*)d_in[13];
    float* out = (float*)d_out;

    __half *xw, *qkv, *attn, *xn2, *h1, *h2, *wqkv, *wproj, *wfc1, *wfc2;
    float  *x2;
    cudaGetSymbolAddress((void**)&xw,    g_xw);
    cudaGetSymbolAddress((void**)&qkv,   g_qkv);
    cudaGetSymbolAddress((void**)&attn,  g_attn);
    cudaGetSymbolAddress((void**)&x2,    g_x2);
    cudaGetSymbolAddress((void**)&xn2,   g_xn2);
    cudaGetSymbolAddress((void**)&h1,    g_h1);
    cudaGetSymbolAddress((void**)&h2,    g_h2);
    cudaGetSymbolAddress((void**)&wqkv,  g_wqkv);
    cudaGetSymbolAddress((void**)&wproj, g_wproj);
    cudaGetSymbolAddress((void**)&wfc1,  g_wfc1);
    cudaGetSymbolAddress((void**)&wfc2,  g_wfc2);

    cudaFuncSetAttribute(hgemm<0, CDIM, 3 * CDIM>, cudaFuncAttributeMaxDynamicSharedMemorySize, GEMM_SMEM);
    cudaFuncSetAttribute(hgemm<2, CDIM, CDIM>,     cudaFuncAttributeMaxDynamicSharedMemorySize, GEMM_SMEM);
    cudaFuncSetAttribute(hgemm<1, CDIM, HID>,      cudaFuncAttributeMaxDynamicSharedMemorySize, GEMM_SMEM);
    cudaFuncSetAttribute(hgemm<3, HID, CDIM>,      cudaFuncAttributeMaxDynamicSharedMemorySize, GEMM_SMEM);

    // 0: wprep qkv
    wprep<<<dim3(1152 / 32, 384 / 32),  dim3(32, 8)>>>(qkvw,  wqkv,  384, 1152);
    // 1: LN1 + roll(-3,-3) + window partition (fp16 out)
    ln_kernel<true><<<MTOT / 8, 256>>>(x, ln1g, ln1b, xw);
    // 2: QKV GEMM
    hgemm<0, CDIM, 3 * CDIM><<<dim3(9, MTOT / 256), 256, GEMM_SMEM>>>(xw, wqkv, qkv, (const float*)0, (const float*)0);
    // 3: wprep proj
    wprep<<<dim3(384 / 32,  384 / 32),  dim3(32, 8)>>>(projw, wproj, 384, 384);
    // 4: windowed attention with analytic shift mask
    attn_kernel<<<dim3(1024, HEADS), 256>>>(qkv, attn);
    // 5: proj GEMM + bias + window-reverse scatter + residual(x) -> x2 (fp32)
    hgemm<2, CDIM, CDIM><<<dim3(3, MTOT / 256), 256, GEMM_SMEM>>>(attn, wproj, x2, projb, x);
    // 6: wprep fc1
    wprep<<<dim3(1536 / 32, 384 / 32),  dim3(32, 8)>>>(fc1w,  wfc1,  384, 1536);
    // 7: LN2 (fp16 out)
    ln_kernel<false><<<MTOT / 8, 256>>>(x2, ln2g, ln2b, xn2);
    // 8: fc1 GEMM + bias
    hgemm<1, CDIM, HID><<<dim3(12, MTOT / 256), 256, GEMM_SMEM>>>(xn2, wfc1, h1, fc1b, (const float*)0);
    // 9: wprep fc2
    wprep<<<dim3(384 / 32,  1536 / 32), dim3(32, 8)>>>(fc2w,  wfc2,  1536, 384);
    // 10: depthwise conv + bias + exact GELU (half2)
    dwconv_gelu<<<dim3(3, NTOK, BATCH), 256>>>(h1, dwk, dwb, h2);
    // 11: fc2 GEMM + bias + residual(x2) -> out (fp32)
    hgemm<3, HID, CDIM><<<dim3(3, MTOT / 256), 256, GEMM_SMEM>>>(h2, wfc2, out, fc2b, x2);
}